// round 8
// baseline (speedup 1.0000x reference)
#include <cuda_runtime.h>
#include <cuda_bf16.h>

#define NN    8000
#define NFEAT 512
#define NHID  128
#define NCLS  64
#define MAXNB 96
#define NIDX  500
#define NGEMMB 125

// ---- scratch (static device globals; no runtime allocation) ----
__device__ float g_h[NN * NHID];        // h = relu(x@W0+b0) == h0
__device__ float g_yhat[NN * NCLS];
__device__ float g_liA[NN * NHID];
__device__ int   g_cols[NN * MAXNB];
__device__ float g_vals[NN * MAXNB];
__device__ int   g_nnz[NN];

// ===============================================================
// K1: heterogeneous front end.
//   blocks [0,125):     GEMM1 64x128 tile + Pseudo + inject + softmax
//   blocks [125,1125):  adjacency ELL extraction (DRAM-bound)
// ===============================================================

// Parallel-ballot group scan: all 4 ballots issue independently;
// positions derived by ALU. Ordering identical to previous rounds.
__device__ __forceinline__ void scan_group_par(float4 v, int base, int lane,
                                               unsigned below, int row, int& count) {
    unsigned m0 = __ballot_sync(~0u, v.x != 0.f);
    unsigned m1 = __ballot_sync(~0u, v.y != 0.f);
    unsigned m2 = __ballot_sync(~0u, v.z != 0.f);
    unsigned m3 = __ballot_sync(~0u, v.w != 0.f);
    if ((m0 | m1 | m2 | m3) == 0u) return;
    int p0 = __popc(m0), p1 = __popc(m1), p2 = __popc(m2), p3 = __popc(m3);
    int idx = base + lane * 4;
    if (v.x != 0.f) { int pos = count + __popc(m0 & below);
                      if (pos < MAXNB) g_cols[row * MAXNB + pos] = idx + 0; }
    if (v.y != 0.f) { int pos = count + p0 + __popc(m1 & below);
                      if (pos < MAXNB) g_cols[row * MAXNB + pos] = idx + 1; }
    if (v.z != 0.f) { int pos = count + p0 + p1 + __popc(m2 & below);
                      if (pos < MAXNB) g_cols[row * MAXNB + pos] = idx + 2; }
    if (v.w != 0.f) { int pos = count + p0 + p1 + p2 + __popc(m3 & below);
                      if (pos < MAXNB) g_cols[row * MAXNB + pos] = idx + 3; }
    count += p0 + p1 + p2 + p3;
}

__global__ void __launch_bounds__(256) k_front(const float* __restrict__ adj,
                                               const float* __restrict__ x,
                                               const float* __restrict__ W0,
                                               const float* __restrict__ b0,
                                               const float* __restrict__ W1,
                                               const float* __restrict__ b1,
                                               const int*   __restrict__ idx,
                                               const float* __restrict__ ylab,
                                               float* __restrict__ outPseudo) {
    __shared__ float As[16][64];          // 4 KB
    __shared__ float Bs[16][128];         // 8 KB
    __shared__ float rowbuf[8][NHID];     // 4 KB
    __shared__ int   s_idx[NIDX];         // 2 KB

    const int tid  = threadIdx.x;
    const int warp = tid >> 5, lane = tid & 31;

    if (blockIdx.x >= NGEMMB) {
        // ---------- adjacency scan: warp/row, depth-2 SW pipeline ----------
        const int row  = (blockIdx.x - NGEMMB) * 8 + warp;
        const float* arow = adj + (size_t)row * NN;
        const float4* arow4 = (const float4*)arow;
        int count = 0;
        const unsigned below = (1u << lane) - 1u;

        // 62 groups of 128 floats (7936). Pairs; prefetch 2 pairs ahead.
        float4 a0 = arow4[0 * 32 + lane];
        float4 a1 = arow4[1 * 32 + lane];
        float4 b0 = arow4[2 * 32 + lane];
        float4 b1 = arow4[3 * 32 + lane];
        float4 c0, c1;
        for (int g = 0; g < 62; g += 2) {
            if (g + 4 < 62) {
                c0 = arow4[(g + 4) * 32 + lane];
                c1 = arow4[(g + 5) * 32 + lane];
            }
            scan_group_par(a0, g * 128, lane, below, row, count);
            scan_group_par(a1, (g + 1) * 128, lane, below, row, count);
            a0 = b0; a1 = b1;
            b0 = c0; b1 = c1;
        }
        {   // tail: 64 floats at 7936
            float2 t = ((const float2*)(arow + 7936))[lane];
            float e[2] = {t.x, t.y};
#pragma unroll
            for (int c = 0; c < 2; c++) {
                unsigned m = __ballot_sync(~0u, e[c] != 0.f);
                if (e[c] != 0.f) {
                    int pos = count + __popc(m & below);
                    if (pos < MAXNB) g_cols[row * MAXNB + pos] = 7936 + lane * 2 + c;
                }
                count += __popc(m);
            }
        }
        if (lane == 0) g_nnz[row] = count < MAXNB ? count : MAXNB;
        return;
    }

    // ---------- GEMM1: 64 rows x 128 cols, K=512, 4x8 microtiles ----------
    const int bRow = blockIdx.x;              // 0..124
    const int tRow = tid >> 4;                // 0..15 -> 4 rows each
    const int tCol = tid & 15;                // 0..15 -> 8 cols each
    const int aRow = tid >> 2;                // 0..63
    const int aK   = (tid & 3) * 4;           // 0,4,8,12
    const int bK   = tid >> 5;                // 0..7 (two k's: bK, bK+8)
    const int bN   = (tid & 31) * 4;          // 0..124

    for (int i = tid; i < NIDX; i += 256) s_idx[i] = idx[i];

    const float* Ag = x + (size_t)(bRow * 64 + aRow) * NFEAT;

    float acc[4][8];
#pragma unroll
    for (int i = 0; i < 4; i++)
#pragma unroll
        for (int j = 0; j < 8; j++) acc[i][j] = 0.f;

    for (int kt = 0; kt < NFEAT; kt += 16) {
        float4 av = *(const float4*)(Ag + kt + aK);
        float4 bv0 = *(const float4*)(W0 + (size_t)(kt + bK) * NHID + bN);
        float4 bv1 = *(const float4*)(W0 + (size_t)(kt + bK + 8) * NHID + bN);
        __syncthreads();   // protect previous iter's reads
        As[aK + 0][aRow] = av.x;
        As[aK + 1][aRow] = av.y;
        As[aK + 2][aRow] = av.z;
        As[aK + 3][aRow] = av.w;
        *(float4*)&Bs[bK][bN]     = bv0;
        *(float4*)&Bs[bK + 8][bN] = bv1;
        __syncthreads();
#pragma unroll
        for (int k = 0; k < 16; k++) {
            float4 rm = *(const float4*)&As[k][tRow * 4];
            float4 rn0 = *(const float4*)&Bs[k][tCol * 8];
            float4 rn1 = *(const float4*)&Bs[k][tCol * 8 + 4];
            float m[4] = {rm.x, rm.y, rm.z, rm.w};
            float n[8] = {rn0.x, rn0.y, rn0.z, rn0.w, rn1.x, rn1.y, rn1.z, rn1.w};
#pragma unroll
            for (int i = 0; i < 4; i++)
#pragma unroll
                for (int j = 0; j < 8; j++) acc[i][j] += m[i] * n[j];
        }
    }
    // epilogue: bias + relu + store h
#pragma unroll
    for (int i = 0; i < 4; i++) {
        int row = bRow * 64 + tRow * 4 + i;
        float4 o0, o1;
        o0.x = acc[i][0] + b0[tCol * 8 + 0];
        o0.y = acc[i][1] + b0[tCol * 8 + 1];
        o0.z = acc[i][2] + b0[tCol * 8 + 2];
        o0.w = acc[i][3] + b0[tCol * 8 + 3];
        o1.x = acc[i][4] + b0[tCol * 8 + 4];
        o1.y = acc[i][5] + b0[tCol * 8 + 5];
        o1.z = acc[i][6] + b0[tCol * 8 + 6];
        o1.w = acc[i][7] + b0[tCol * 8 + 7];
        o0.x = o0.x > 0.f ? o0.x : 0.f;  o0.y = o0.y > 0.f ? o0.y : 0.f;
        o0.z = o0.z > 0.f ? o0.z : 0.f;  o0.w = o0.w > 0.f ? o0.w : 0.f;
        o1.x = o1.x > 0.f ? o1.x : 0.f;  o1.y = o1.y > 0.f ? o1.y : 0.f;
        o1.z = o1.z > 0.f ? o1.z : 0.f;  o1.w = o1.w > 0.f ? o1.w : 0.f;
        *(float4*)(g_h + (size_t)row * NHID + tCol * 8)     = o0;
        *(float4*)(g_h + (size_t)row * NHID + tCol * 8 + 4) = o1;
    }
    __syncthreads();   // block's g_h writes visible block-wide

    // ---------- Pseudo + inject + softmax for this block's 64 rows ----------
    for (int rr = 0; rr < 8; rr++) {
        const int row = bRow * 64 + warp * 8 + rr;
        float4 hv = *(const float4*)(g_h + (size_t)row * NHID + lane * 4); // L1 hit
        *(float4*)&rowbuf[warp][lane * 4] = hv;
        __syncwarp();

        int lo = 0, hi = NIDX;
        while (lo < hi) { int mid = (lo + hi) >> 1; if (s_idx[mid] < row) lo = mid + 1; else hi = mid; }
        int lb = lo; hi = NIDX;
        while (lo < hi) { int mid = (lo + hi) >> 1; if (s_idx[mid] <= row) lo = mid + 1; else hi = mid; }
        const float cf = 0.1f * (float)(lo - lb);

        const int c0 = lane * 2, c1 = c0 + 1;
        float a0 = b1[c0], a1 = b1[c1];
#pragma unroll 8
        for (int k = 0; k < NHID; k++) {
            float hk = rowbuf[warp][k];
            float2 w = *(const float2*)(W1 + k * NCLS + c0);
            a0 += hk * w.x;
            a1 += hk * w.y;
        }
        if (cf != 0.f) {
            a0 += cf * ylab[row * NCLS + c0];
            a1 += cf * ylab[row * NCLS + c1];
        }
        float2 p; p.x = a0; p.y = a1;
        *(float2*)(outPseudo + row * NCLS + c0) = p;

        float m = fmaxf(a0, a1);
#pragma unroll
        for (int o = 16; o; o >>= 1) m = fmaxf(m, __shfl_xor_sync(~0u, m, o));
        float e0 = expf(a0 - m), e1 = expf(a1 - m);
        float s = e0 + e1;
#pragma unroll
        for (int o = 16; o; o >>= 1) s += __shfl_xor_sync(~0u, s, o);
        float inv = 1.f / s;
        float2 y; y.x = e0 * inv; y.y = e1 * inv;
        *(float2*)(g_yhat + row * NCLS + c0) = y;
        __syncwarp();
    }
}

// ===============================================================
// K2: mask weights + SpMM layer 0 + residual + L2 norm -> liA.
// ===============================================================
__global__ void __launch_bounds__(256) k_mask_spmm0() {
    __shared__ float vals_s[8][MAXNB];
    __shared__ int   cols_s[8][MAXNB];
    const int warp = threadIdx.x >> 5, lane = threadIdx.x & 31;
    const int row  = blockIdx.x * 8 + warp;
    const int nnz  = g_nnz[row];
    const int off  = row * MAXNB;
    for (int k = lane; k < nnz; k += 32) cols_s[warp][k] = g_cols[off + k];
    __syncwarp();

    float2 yi = *(const float2*)(g_yhat + row * NCLS + lane * 2);
    float rsum = 0.f;
    for (int k = 0; k < nnz; k++) {
        int c = cols_s[warp][k];
        float2 yj = *(const float2*)(g_yhat + c * NCLS + lane * 2);
        float d = yi.x * yj.x + yi.y * yj.y;
#pragma unroll
        for (int o = 16; o; o >>= 1) d += __shfl_xor_sync(~0u, d, o);
        if (lane == 0) vals_s[warp][k] = d;
        rsum += d;
    }
    __syncwarp();
    const float inv = 1.f / fmaxf(rsum, 1e-12f);
    for (int k = lane; k < nnz; k += 32) g_vals[off + k] = vals_s[warp][k] * inv;
    __syncwarp();

    float4 acc = make_float4(0.f, 0.f, 0.f, 0.f);
    for (int k = 0; k < nnz; k++) {
        int   c = cols_s[warp][k];
        float w = vals_s[warp][k] * inv;
        float4 v = *(const float4*)(g_h + (size_t)c * NHID + lane * 4);
        acc.x += w * v.x; acc.y += w * v.y; acc.z += w * v.z; acc.w += w * v.w;
    }
    float4 h0 = *(const float4*)(g_h + (size_t)row * NHID + lane * 4);
    float4 r;
    r.x = 0.9f * acc.x + 0.1f * h0.x;
    r.y = 0.9f * acc.y + 0.1f * h0.y;
    r.z = 0.9f * acc.z + 0.1f * h0.z;
    r.w = 0.9f * acc.w + 0.1f * h0.w;
    float ss = r.x * r.x + r.y * r.y + r.z * r.z + r.w * r.w;
#pragma unroll
    for (int o = 16; o; o >>= 1) ss += __shfl_xor_sync(~0u, ss, o);
    float ninv = 1.f / fmaxf(sqrtf(ss), 1e-12f);
    r.x *= ninv; r.y *= ninv; r.z *= ninv; r.w *= ninv;
    *(float4*)(g_liA + (size_t)row * NHID + lane * 4) = r;
}

// ===============================================================
// K3: SpMM layer 1 + residual + L2 norm, then
//     out = log_softmax(liB_row @ W2 + b2).
// ===============================================================
__global__ void __launch_bounds__(256) k_spmm1_out(const float* __restrict__ W2,
                                                   const float* __restrict__ b2,
                                                   float* __restrict__ out) {
    __shared__ float Ws[NHID * NCLS];
    __shared__ float bs[NCLS];
    __shared__ float rowbuf[8][NHID];
    const int tid = threadIdx.x;
    for (int i = tid; i < NHID * NCLS; i += 256) Ws[i] = W2[i];
    if (tid < NCLS) bs[tid] = b2[tid];
    __syncthreads();

    const int warp = tid >> 5, lane = tid & 31;
    const int row  = blockIdx.x * 8 + warp;
    const int nnz  = g_nnz[row];
    const int off  = row * MAXNB;

    float4 acc = make_float4(0.f, 0.f, 0.f, 0.f);
    for (int k = 0; k < nnz; k++) {
        int   c = g_cols[off + k];
        float w = g_vals[off + k];
        float4 v = *(const float4*)(g_liA + (size_t)c * NHID + lane * 4);
        acc.x += w * v.x; acc.y += w * v.y; acc.z += w * v.z; acc.w += w * v.w;
    }
    float4 h0 = *(const float4*)(g_h + (size_t)row * NHID + lane * 4);
    float4 r;
    r.x = 0.9f * acc.x + 0.1f * h0.x;
    r.y = 0.9f * acc.y + 0.1f * h0.y;
    r.z = 0.9f * acc.z + 0.1f * h0.z;
    r.w = 0.9f * acc.w + 0.1f * h0.w;
    float ss = r.x * r.x + r.y * r.y + r.z * r.z + r.w * r.w;
#pragma unroll
    for (int o = 16; o; o >>= 1) ss += __shfl_xor_sync(~0u, ss, o);
    float ninv = 1.f / fmaxf(sqrtf(ss), 1e-12f);
    r.x *= ninv; r.y *= ninv; r.z *= ninv; r.w *= ninv;
    *(float4*)&rowbuf[warp][lane * 4] = r;
    __syncwarp();

    const int c0 = lane * 2, c1 = c0 + 1;
    float a0 = bs[c0], a1 = bs[c1];
#pragma unroll 8
    for (int k = 0; k < NHID; k++) {
        float hk = rowbuf[warp][k];
        float2 w = *(const float2*)&Ws[k * NCLS + c0];
        a0 += hk * w.x;
        a1 += hk * w.y;
    }
    float m = fmaxf(a0, a1);
#pragma unroll
    for (int o = 16; o; o >>= 1) m = fmaxf(m, __shfl_xor_sync(~0u, m, o));
    float e0 = expf(a0 - m), e1 = expf(a1 - m);
    float s = e0 + e1;
#pragma unroll
    for (int o = 16; o; o >>= 1) s += __shfl_xor_sync(~0u, s, o);
    float ls = logf(s);
    out[row * NCLS + c0] = a0 - m - ls;
    out[row * NCLS + c1] = a1 - m - ls;
}

extern "C" void kernel_launch(void* const* d_in, const int* in_sizes, int n_in,
                              void* d_out, int out_size) {
    const float* x    = (const float*)d_in[0];
    const float* adj  = (const float*)d_in[1];
    const float* ylab = (const float*)d_in[2];
    const int*   idx  = (const int*)  d_in[3];
    const float* W0   = (const float*)d_in[4];
    const float* b0   = (const float*)d_in[5];
    const float* W1   = (const float*)d_in[6];
    const float* b1   = (const float*)d_in[7];
    const float* W2   = (const float*)d_in[8];
    const float* b2   = (const float*)d_in[9];
    float* out = (float*)d_out;                  // [log_softmax | Pseudo]

    k_front<<<1125, 256>>>(adj, x, W0, b0, W1, b1, idx, ylab, out + NN * NCLS);
    k_mask_spmm0<<<1000, 256>>>();
    k_spmm1_out<<<1000, 256>>>(W2, b2, out);
}